// round 3
// baseline (speedup 1.0000x reference)
#include <cuda_runtime.h>
#include <math.h>

// Problem constants
#define Bz 4
#define Cz 12
#define Hh 256
#define Ww 256
#define HW 65536            // Hh*Ww
#define NMASK 96            // 2*Bz*Cz
#define HALFM 48            // Bz*Cz
#define SENT16 65535u
#define SENT_LL 1000000000000LL
#define SENT_F 1e12f        // == fl32(1e6f * 1e6f), matches reference LARGE^2

// ---------------- scratch (static device globals; no allocations) ------------
__device__ unsigned char g_mask[NMASK * HW];     // 6.3 MB
__device__ unsigned int  g_g[NMASK * HW];        // 25 MB: packed column dist (lo=fg, hi=bg)
__device__ float2        g_d2[NMASK * HW];       // 50 MB: squared EDT {fg, bg}
__device__ int           g_hasfg[NMASK];
__device__ double        g_acc[2];               // [0]=hausdorff sum, [1]=sum logp_t
__device__ int           g_is64;

// ---------------- K0: zero accumulators + detect target dtype ----------------
__global__ void k0_init(const unsigned int* tgt_words) {
    if (threadIdx.x == 0) {
        g_acc[0] = 0.0;
        g_acc[1] = 0.0;
        int is64 = 1;
        for (int i = 0; i < 128; i++) {
            if (tgt_words[2 * i + 1] != 0u) { is64 = 0; break; }
        }
        g_is64 = is64;
    }
}

__device__ __forceinline__ int load_target(const void* t, int idx) {
    if (g_is64) return (int)((const long long*)t)[idx];
    return ((const int*)t)[idx];
}

// ---------------- K1: softmax -> masks, cross-entropy partial ----------------
__global__ void k1_masks(const float* __restrict__ pred, const void* __restrict__ tgt) {
    int pix = blockIdx.x * 256 + threadIdx.x;   // 0 .. Bz*HW-1
    int b = pix >> 16;
    int hw = pix & (HW - 1);
    const float* p = pred + (size_t)b * Cz * HW + hw;

    int t = load_target(tgt, pix);

    float v[Cz];
    float mx = -1e30f;
    float xt = 0.0f;
#pragma unroll
    for (int c = 0; c < Cz; c++) {
        v[c] = p[c * HW];
        mx = fmaxf(mx, v[c]);
        if (c == t) xt = v[c];
    }
    float s = 0.0f;
#pragma unroll
    for (int c = 0; c < Cz; c++) {
        v[c] = expf(v[c] - mx);
        s += v[c];
    }
    float inv = 1.0f / s;
#pragma unroll
    for (int c = 0; c < Cz; c++) {
        g_mask[(size_t)(b * Cz + c) * HW + hw] = (unsigned char)(v[c] * inv > 0.5f);
        g_mask[(size_t)(HALFM + b * Cz + c) * HW + hw] = (unsigned char)(c == t);
    }

    float logp = xt - mx - logf(s);

    __shared__ float sred[256];
    sred[threadIdx.x] = logp;
    __syncthreads();
    for (int st = 128; st > 0; st >>= 1) {
        if (threadIdx.x < st) sred[threadIdx.x] += sred[threadIdx.x + st];
        __syncthreads();
    }
    if (threadIdx.x == 0) atomicAdd(&g_acc[1], (double)sred[0]);
}

// ---------------- K2: column 1D distance (both polarities) + has_fg ----------
// One block per mask, one thread per column w. Integer distances, sentinel 65535.
// .lo: feature = ~mask (edt(mask)), .hi: feature = mask (edt(~mask)).
__global__ void k2_cols() {
    int m = blockIdx.x;
    int w = threadIdx.x;
    const unsigned char* msk = g_mask + (size_t)m * HW;
    unsigned int* gg = g_g + (size_t)m * HW;

    int c1 = (int)SENT16, c2 = (int)SENT16;
    int any = 0;
#pragma unroll 4
    for (int h = 0; h < Hh; h++) {
        int mv = msk[h * Ww + w];
        any |= mv;
        c1 = mv ? min(c1 + 1, (int)SENT16) : 0;   // feature = ~mask
        c2 = mv ? 0 : min(c2 + 1, (int)SENT16);   // feature =  mask
        gg[h * Ww + w] = (unsigned int)c1 | ((unsigned int)c2 << 16);
    }
    c1 = (int)SENT16; c2 = (int)SENT16;
#pragma unroll 4
    for (int h = Hh - 1; h >= 0; h--) {
        int mv = msk[h * Ww + w];
        c1 = mv ? min(c1 + 1, (int)SENT16) : 0;
        c2 = mv ? 0 : min(c2 + 1, (int)SENT16);
        unsigned int f = gg[h * Ww + w];
        int g1 = min((int)(f & 0xffffu), c1);
        int g2v = min((int)(f >> 16), c2);
        gg[h * Ww + w] = (unsigned int)g1 | ((unsigned int)g2v << 16);
    }

    __shared__ int sany[256];
    sany[w] = any;
    __syncthreads();
    for (int st = 128; st > 0; st >>= 1) {
        if (w < st) sany[w] |= sany[w + st];
        __syncthreads();
    }
    if (w == 0) g_hasfg[m] = sany[0];
}

// ---------------- K3: Felzenszwalb lower-envelope row pass (exact) -----------
// One thread per (mask, row, polarity). Envelope decisions done in exact int64
// rational arithmetic; final d2 values computed with the same fp32 ops as the
// reference brute force, so results are bit-identical.
__device__ __forceinline__ long long fval_ll(const unsigned int* row, int j, int pol) {
    unsigned int p = row[j];
    unsigned int g = pol ? (p >> 16) : (p & 0xffffu);
    return (g == SENT16) ? SENT_LL : (long long)(g * g);
}

__global__ void k3_rows() {
    int gid = blockIdx.x * 256 + threadIdx.x;   // 0 .. 49151
    int pol = gid & 1;
    int rid = gid >> 1;                          // 0 .. 24575
    int m = rid >> 8;
    int h = rid & 255;

    const unsigned int* row = g_g + (size_t)m * HW + (size_t)h * Ww;
    float* out = (float*)g_d2 + ((size_t)m * HW + (size_t)h * Ww) * 2 + pol;

    short v[Ww];                                 // envelope vertices (local mem)

    // ---- pass 1: build envelope ----
    int k = 0;
    v[0] = 0;
    for (int q = 1; q < Ww; q++) {
        long long Fq = fval_ll(row, q, pol);
        while (true) {
            int p = v[k];
            long long Fp = fval_ll(row, p, pol);
            long long nq = Fq - Fp + (long long)(q * q - p * p);
            int dq = 2 * (q - p);
            if (k == 0) break;
            int p2 = v[k - 1];
            long long Fp2 = fval_ll(row, p2, pol);
            long long nt = Fp - Fp2 + (long long)(p * p - p2 * p2);
            int dt = 2 * (p - p2);
            // s(p,q) <= s(p2,p)  <=>  nq/dq <= nt/dt  <=>  nq*dt <= nt*dq
            if (nq * (long long)dt <= nt * (long long)dq) { k--; }
            else break;
        }
        v[++k] = (short)q;
    }

    // ---- pass 2: evaluate ----
    int r = 0;
    long long zn = 0; long long zd = 0;
    if (r < k) {
        int p = v[0], pn = v[1];
        zn = fval_ll(row, pn, pol) - fval_ll(row, p, pol) + (long long)(pn * pn - p * p);
        zd = (long long)(2 * (pn - p));
    }
    for (int q = 0; q < Ww; q++) {
        while (r < k && zn < (long long)q * zd) {
            r++;
            if (r < k) {
                int p = v[r], pn = v[r + 1];
                zn = fval_ll(row, pn, pol) - fval_ll(row, p, pol) + (long long)(pn * pn - p * p);
                zd = (long long)(2 * (pn - p));
            }
        }
        int p = v[r];
        unsigned int pv = row[p];
        unsigned int g = pol ? (pv >> 16) : (pv & 0xffffu);
        float fv = (g == SENT16) ? SENT_F : (float)(g * g);
        int dj = q - p;
        out[q * 2] = fv + (float)(dj * dj);      // same fp32 ops as reference
    }
}

// ---------------- K4: hausdorff loss reduction -------------------------------
__global__ void k4_loss(const float* __restrict__ pred, const void* __restrict__ tgt) {
    int pix = blockIdx.x * 256 + threadIdx.x;
    int b = pix >> 16;
    int hw = pix & (HW - 1);
    const float* p = pred + (size_t)b * Cz * HW + hw;

    int t = load_target(tgt, pix);

    float v[Cz];
    float mx = -1e30f;
#pragma unroll
    for (int c = 0; c < Cz; c++) {
        v[c] = p[c * HW];
        mx = fmaxf(mx, v[c]);
    }
    float s = 0.0f;
#pragma unroll
    for (int c = 0; c < Cz; c++) {
        v[c] = expf(v[c] - mx);
        s += v[c];
    }
    float inv = 1.0f / s;

    double acc = 0.0;
#pragma unroll
    for (int c = 0; c < Cz; c++) {
        int mP = b * Cz + c;
        int mT = HALFM + b * Cz + c;
        float2 dP = g_d2[(size_t)mP * HW + hw];
        float2 dT = g_d2[(size_t)mT * HW + hw];
        // field^2 = (sqrt(a)+sqrt(b))^2 = a + b + 2*sqrt(a*b)
        float fP2 = g_hasfg[mP] ? (dP.x + dP.y + 2.0f * __fsqrt_rn(dP.x * dP.y)) : 0.0f;
        float fT2 = g_hasfg[mT] ? (dT.x + dT.y + 2.0f * __fsqrt_rn(dT.x * dT.y)) : 0.0f;
        float dist = fP2 + fT2;
        float e = v[c] * inv - ((c == t) ? 1.0f : 0.0f);
        acc += (double)(e * e * dist);
    }

    __shared__ double sred[256];
    sred[threadIdx.x] = acc;
    __syncthreads();
    for (int st = 128; st > 0; st >>= 1) {
        if (threadIdx.x < st) sred[threadIdx.x] += sred[threadIdx.x + st];
        __syncthreads();
    }
    if (threadIdx.x == 0) atomicAdd(&g_acc[0], sred[0]);
}

// ---------------- K5: finalize ----------------------------------------------
__global__ void k5_final(float* out) {
    if (threadIdx.x == 0) {
        double S  = g_acc[0];
        double CE = g_acc[1];
        double N = (double)Bz * (double)HW;
        double loss = S / N / (double)Cz / (double)Bz / 3.0 - CE / N;
        out[0] = (float)loss;
    }
}

// ---------------- launch -----------------------------------------------------
extern "C" void kernel_launch(void* const* d_in, const int* in_sizes, int n_in,
                              void* d_out, int out_size) {
    const float* pred = (const float*)d_in[0];
    const void*  tgt  = d_in[1];
    float* out = (float*)d_out;

    k0_init<<<1, 32>>>((const unsigned int*)tgt);
    k1_masks<<<(Bz * HW) / 256, 256>>>(pred, tgt);
    k2_cols<<<NMASK, 256>>>();
    k3_rows<<<(NMASK * Hh * 2) / 256, 256>>>();
    k4_loss<<<(Bz * HW) / 256, 256>>>(pred, tgt);
    k5_final<<<1, 32>>>(out);
    (void)in_sizes; (void)n_in; (void)out_size;
}

// round 4
// speedup vs baseline: 3.2890x; 3.2890x over previous
#include <cuda_runtime.h>
#include <math.h>

// Problem constants
#define Bz 4
#define Cz 12
#define Hh 256
#define Ww 256
#define HW 65536            // Hh*Ww
#define NMASK 96            // 2*Bz*Cz
#define HALFM 48            // Bz*Cz
#define SENT16 65535u
#define BIGI (1 << 28)
#define SENT_F 1e12f        // == fl32(1e6f*1e6f)
#define SCAN_INF (1 << 20)

// ---------------- scratch (static device globals; no allocations) ------------
__device__ unsigned char g_mask[NMASK * HW];     // 6.3 MB
__device__ unsigned int  g_g[NMASK * HW];        // 25 MB packed col dist (lo=fg, hi=bg)
__device__ float         g_d2f[NMASK * HW];      // 25 MB squared EDT, fg polarity
__device__ float         g_d2b[NMASK * HW];      // 25 MB squared EDT, bg polarity
__device__ int           g_hasfg[NMASK];
__device__ double        g_acc[2];
__device__ int           g_is64;

// ---------------- K0 ---------------------------------------------------------
__global__ void k0_init(const unsigned int* tgt_words) {
    if (threadIdx.x == 0) {
        g_acc[0] = 0.0;
        g_acc[1] = 0.0;
        int is64 = 1;
        for (int i = 0; i < 128; i++) {
            if (tgt_words[2 * i + 1] != 0u) { is64 = 0; break; }
        }
        g_is64 = is64;
    }
}

__device__ __forceinline__ int load_target(const void* t, int idx) {
    if (g_is64) return (int)((const long long*)t)[idx];
    return ((const int*)t)[idx];
}

// ---------------- K1: softmax -> masks, CE partial ---------------------------
__global__ void k1_masks(const float* __restrict__ pred, const void* __restrict__ tgt) {
    int pix = blockIdx.x * 256 + threadIdx.x;
    int b = pix >> 16;
    int hw = pix & (HW - 1);
    const float* p = pred + (size_t)b * Cz * HW + hw;

    int t = load_target(tgt, pix);

    float v[Cz];
    float mx = -1e30f;
    float xt = 0.0f;
#pragma unroll
    for (int c = 0; c < Cz; c++) {
        v[c] = p[c * HW];
        mx = fmaxf(mx, v[c]);
        if (c == t) xt = v[c];
    }
    float s = 0.0f;
#pragma unroll
    for (int c = 0; c < Cz; c++) {
        v[c] = expf(v[c] - mx);
        s += v[c];
    }
    float inv = 1.0f / s;
#pragma unroll
    for (int c = 0; c < Cz; c++) {
        g_mask[(size_t)(b * Cz + c) * HW + hw] = (unsigned char)(v[c] * inv > 0.5f);
        g_mask[(size_t)(HALFM + b * Cz + c) * HW + hw] = (unsigned char)(c == t);
    }

    float logp = xt - mx - logf(s);

    __shared__ float sred[256];
    sred[threadIdx.x] = logp;
    __syncthreads();
    for (int st = 128; st > 0; st >>= 1) {
        if (threadIdx.x < st) sred[threadIdx.x] += sred[threadIdx.x + st];
        __syncthreads();
    }
    if (threadIdx.x == 0) atomicAdd(&g_acc[1], (double)sred[0]);
}

// ---------------- K2: column 1D distance (both polarities) + has_fg ----------
__global__ void k2_cols() {
    int m = blockIdx.x;
    int w = threadIdx.x;
    const unsigned char* msk = g_mask + (size_t)m * HW;
    unsigned int* gg = g_g + (size_t)m * HW;

    int c1 = (int)SENT16, c2 = (int)SENT16;
    int any = 0;
#pragma unroll 4
    for (int h = 0; h < Hh; h++) {
        int mv = msk[h * Ww + w];
        any |= mv;
        c1 = mv ? min(c1 + 1, (int)SENT16) : 0;
        c2 = mv ? 0 : min(c2 + 1, (int)SENT16);
        gg[h * Ww + w] = (unsigned int)c1 | ((unsigned int)c2 << 16);
    }
    c1 = (int)SENT16; c2 = (int)SENT16;
#pragma unroll 4
    for (int h = Hh - 1; h >= 0; h--) {
        int mv = msk[h * Ww + w];
        c1 = mv ? min(c1 + 1, (int)SENT16) : 0;
        c2 = mv ? 0 : min(c2 + 1, (int)SENT16);
        unsigned int f = gg[h * Ww + w];
        int g1 = min((int)(f & 0xffffu), c1);
        int g2v = min((int)(f >> 16), c2);
        gg[h * Ww + w] = (unsigned int)g1 | ((unsigned int)g2v << 16);
    }

    __shared__ int sany[256];
    sany[w] = any;
    __syncthreads();
    for (int st = 128; st > 0; st >>= 1) {
        if (w < st) sany[w] |= sany[w + st];
        __syncthreads();
    }
    if (w == 0) g_hasfg[m] = sany[0];
}

// ---------------- K3: exact windowed row pass --------------------------------
// Block: (mask, 4 rows), 8 warps = 4 rows x 2 polarities. Warp-private work:
//   1. load g row, g2 into padded smem (pads = BIGI)
//   2. chamfer bound ub[j] = min_j' (g[j'] + |j-j'|)  via warp scans (exact bound)
//   3. window scan |delta| <= min(ub,255): candidates are always valid =>
//      result == full brute force == reference (integer-exact).
__global__ void __launch_bounds__(256) k3_win() {
    __shared__ int sg2[8][768];              // [warp][256 pad | 256 data | 256 pad]
    __shared__ unsigned char sub[8][256];

    int tid = threadIdx.x;
    int w = tid >> 5;
    int lane = tid & 31;
    int r = w >> 1;
    int pol = w & 1;
    int m = blockIdx.x;
    int row = blockIdx.y * 4 + r;

    const unsigned int* grow = g_g + (size_t)m * HW + (size_t)row * Ww;
    float* out = (pol ? g_d2b : g_d2f) + (size_t)m * HW + (size_t)row * Ww;

    // init whole array (incl pads) to BIGI
#pragma unroll
    for (int i = lane; i < 768; i += 32) sg2[w][i] = BIGI;

    // load + extract this polarity
    int base = lane * 8;
    const uint4* grow4 = (const uint4*)grow;
    uint4 q0 = grow4[lane * 2 + 0];
    uint4 q1 = grow4[lane * 2 + 1];
    unsigned int gp8[8] = {q0.x, q0.y, q0.z, q0.w, q1.x, q1.y, q1.z, q1.w};

    int x[8];
    int anyfin = 0;
#pragma unroll
    for (int i = 0; i < 8; i++) {
        unsigned int g = pol ? (gp8[i] >> 16) : (gp8[i] & 0xffffu);
        int fin = (g != SENT16);
        anyfin |= fin;
        sg2[w][256 + base + i] = fin ? (int)(g * g) : BIGI;
        x[i] = fin ? (int)g : 300;           // cap sentinel for chamfer (safe: see proof)
    }

    // all-sentinel row: result is exactly 1e12 everywhere
    if (__ballot_sync(0xffffffffu, anyfin) == 0u) {
#pragma unroll
        for (int i = 0; i < 8; i++) out[i * 32 + lane] = SENT_F;
        return;
    }

    // forward chamfer: f[j] = min_{j'<=j} x[j'] + (j-j')
    int f[8];
    int run = SCAN_INF;
#pragma unroll
    for (int i = 0; i < 8; i++) { run = min(x[i], run + 1); f[i] = run; }
    int v = run;                              // segment summary @ last elem
#pragma unroll
    for (int s = 1; s < 32; s <<= 1) {
        int o = __shfl_up_sync(0xffffffffu, v, s);
        if (lane >= s) v = min(v, o + 8 * s);
    }
    int e = __shfl_up_sync(0xffffffffu, v, 1);
    if (lane == 0) e = SCAN_INF;
#pragma unroll
    for (int i = 0; i < 8; i++) f[i] = min(f[i], e + 1 + i);

    // backward chamfer
    int bw[8];
    run = SCAN_INF;
#pragma unroll
    for (int i = 7; i >= 0; i--) { run = min(x[i], run + 1); bw[i] = run; }
    int vb = run;                             // summary @ first elem
#pragma unroll
    for (int s = 1; s < 32; s <<= 1) {
        int o = __shfl_down_sync(0xffffffffu, vb, s);
        if (lane + s < 32) vb = min(vb, o + 8 * s);
    }
    int eb = __shfl_down_sync(0xffffffffu, vb, 1);
    if (lane == 31) eb = SCAN_INF;
#pragma unroll
    for (int i = 0; i < 8; i++) {
        int ub = min(min(f[i], bw[i]), min(eb + 8 - i, 255));
        sub[w][base + i] = (unsigned char)ub;
    }
    __syncwarp();

    // window scan: strided output layout, warp-uniform radius
    const int* gp = &sg2[w][256];
#pragma unroll
    for (int i = 0; i < 8; i++) {
        int j = i * 32 + lane;
        int R = (int)sub[w][j];
        R = __reduce_max_sync(0xffffffffu, R);
        int best = gp[j];
#pragma unroll 4
        for (int d = 1; d <= R; d++) {
            int c1 = gp[j + d] + d * d;
            int c2 = gp[j - d] + d * d;
            best = min(best, min(c1, c2));
        }
        out[j] = (best >= BIGI) ? SENT_F : (float)best;
    }
}

// ---------------- K4: hausdorff loss reduction -------------------------------
__global__ void k4_loss(const float* __restrict__ pred, const void* __restrict__ tgt) {
    int pix = blockIdx.x * 256 + threadIdx.x;
    int b = pix >> 16;
    int hw = pix & (HW - 1);
    const float* p = pred + (size_t)b * Cz * HW + hw;

    int t = load_target(tgt, pix);

    float v[Cz];
    float mx = -1e30f;
#pragma unroll
    for (int c = 0; c < Cz; c++) {
        v[c] = p[c * HW];
        mx = fmaxf(mx, v[c]);
    }
    float s = 0.0f;
#pragma unroll
    for (int c = 0; c < Cz; c++) {
        v[c] = expf(v[c] - mx);
        s += v[c];
    }
    float inv = 1.0f / s;

    double acc = 0.0;
#pragma unroll
    for (int c = 0; c < Cz; c++) {
        int mP = b * Cz + c;
        int mT = HALFM + b * Cz + c;
        float aP = g_d2f[(size_t)mP * HW + hw];
        float bP = g_d2b[(size_t)mP * HW + hw];
        float aT = g_d2f[(size_t)mT * HW + hw];
        float bT = g_d2b[(size_t)mT * HW + hw];
        // field^2 = (sqrt(a)+sqrt(b))^2 = a + b + 2*sqrt(a*b)
        float fP2 = g_hasfg[mP] ? (aP + bP + 2.0f * __fsqrt_rn(aP * bP)) : 0.0f;
        float fT2 = g_hasfg[mT] ? (aT + bT + 2.0f * __fsqrt_rn(aT * bT)) : 0.0f;
        float dist = fP2 + fT2;
        float e = v[c] * inv - ((c == t) ? 1.0f : 0.0f);
        acc += (double)(e * e * dist);
    }

    __shared__ double sred[256];
    sred[threadIdx.x] = acc;
    __syncthreads();
    for (int st = 128; st > 0; st >>= 1) {
        if (threadIdx.x < st) sred[threadIdx.x] += sred[threadIdx.x + st];
        __syncthreads();
    }
    if (threadIdx.x == 0) atomicAdd(&g_acc[0], sred[0]);
}

// ---------------- K5: finalize ----------------------------------------------
__global__ void k5_final(float* out) {
    if (threadIdx.x == 0) {
        double S  = g_acc[0];
        double CE = g_acc[1];
        double N = (double)Bz * (double)HW;
        double loss = S / N / (double)Cz / (double)Bz / 3.0 - CE / N;
        out[0] = (float)loss;
    }
}

// ---------------- launch -----------------------------------------------------
extern "C" void kernel_launch(void* const* d_in, const int* in_sizes, int n_in,
                              void* d_out, int out_size) {
    const float* pred = (const float*)d_in[0];
    const void*  tgt  = d_in[1];
    float* out = (float*)d_out;

    k0_init<<<1, 32>>>((const unsigned int*)tgt);
    k1_masks<<<(Bz * HW) / 256, 256>>>(pred, tgt);
    k2_cols<<<NMASK, 256>>>();
    k3_win<<<dim3(NMASK, Hh / 4), 256>>>();
    k4_loss<<<(Bz * HW) / 256, 256>>>(pred, tgt);
    k5_final<<<1, 32>>>(out);
    (void)in_sizes; (void)n_in; (void)out_size;
}

// round 6
// speedup vs baseline: 6.7321x; 2.0469x over previous
#include <cuda_runtime.h>
#include <math.h>

// Problem constants
#define Bz 4
#define Cz 12
#define Hh 256
#define Ww 256
#define HW 65536
#define NMASK 96
#define HALFM 48
#define SENT16 65535u
#define BIGI (1 << 28)
#define SENT_F 1e12f        // == fl32(1e6f*1e6f)
#define SCAN_INF (1 << 20)
#define CFAKE 10000         // > any real distance (255), carry-fake sentinel

// ---------------- scratch ----------------------------------------------------
__device__ unsigned char g_mask[NMASK * HW];     // 6.3 MB
__device__ unsigned int  g_g[NMASK * HW];        // 25 MB packed col dist (lo=fg, hi=bg)
__device__ float         g_f2[NMASK * HW];       // 25 MB field^2 per mask
__device__ int           g_hasfg[NMASK];
__device__ double        g_acc[2];               // [0]=hausdorff sum, [1]=sum logp_t
__device__ int           g_is64;
__device__ unsigned int  g_done;

// ---------------- K0: parallel init + dtype detect ---------------------------
__global__ void k0_init(const unsigned int* __restrict__ tgt_words) {
    int t = threadIdx.x;                          // 128 threads
    __shared__ int s_nz;
    if (t == 0) s_nz = 0;
    __syncthreads();
    if (tgt_words[2 * t + 1] != 0u) atomicOr(&s_nz, 1);
    if (t < NMASK) g_hasfg[t] = 0;
    __syncthreads();
    if (t == 0) {
        g_is64 = (s_nz == 0);
        g_acc[0] = 0.0;
        g_acc[1] = 0.0;
        g_done = 0u;
    }
}

__device__ __forceinline__ int load_target(const void* t, int idx) {
    if (g_is64) return (int)((const long long*)t)[idx];
    return ((const int*)t)[idx];
}

// ---------------- K1: softmax -> masks, CE partial ---------------------------
__global__ void k1_masks(const float* __restrict__ pred, const void* __restrict__ tgt) {
    int pix = blockIdx.x * 256 + threadIdx.x;
    int b = pix >> 16;
    int hw = pix & (HW - 1);
    const float* p = pred + (size_t)b * Cz * HW + hw;

    int t = load_target(tgt, pix);

    float v[Cz];
    float mx = -1e30f;
    float xt = 0.0f;
#pragma unroll
    for (int c = 0; c < Cz; c++) {
        v[c] = p[c * HW];
        mx = fmaxf(mx, v[c]);
        if (c == t) xt = v[c];
    }
    float s = 0.0f;
#pragma unroll
    for (int c = 0; c < Cz; c++) {
        v[c] = expf(v[c] - mx);
        s += v[c];
    }
    float inv = 1.0f / s;
#pragma unroll
    for (int c = 0; c < Cz; c++) {
        g_mask[(size_t)(b * Cz + c) * HW + hw] = (unsigned char)(v[c] * inv > 0.5f);
        g_mask[(size_t)(HALFM + b * Cz + c) * HW + hw] = (unsigned char)(c == t);
    }

    float logp = xt - mx - logf(s);

    __shared__ float sred[256];
    sred[threadIdx.x] = logp;
    __syncthreads();
    for (int st = 128; st > 0; st >>= 1) {
        if (threadIdx.x < st) sred[threadIdx.x] += sred[threadIdx.x + st];
        __syncthreads();
    }
    if (threadIdx.x == 0) atomicAdd(&g_acc[1], (double)sred[0]);
}

// ---------------- K2: segmented column EDT (exact) ---------------------------
// grid (NMASK, 4): block = 64 columns x 4 H-segments of 64. Forward local scan
// stages saturated-u8 values in smem (exact: in-segment finite values <= 63;
// 255 <=> local-infinity; true distances <= 255 when the column has a feature,
// so a fake 255 can only tie, never beat, a true value; empty columns are
// detected via per-segment first-feature summaries and forced to SENT16).
__global__ void __launch_bounds__(256) k2_cols() {
    __shared__ unsigned short sfwd[Hh][64];       // packed u8: c1 | c2<<8
    __shared__ unsigned short ssum[2][4][64];     // [0]=chain-end, [1]=first-feature

    int tid = threadIdx.x;
    int col = tid & 63;
    int seg = tid >> 6;
    int m = blockIdx.x;
    int w = blockIdx.y * 64 + col;
    const unsigned char* msk = g_mask + (size_t)m * HW + w;

    // phase 1: local forward scan for segment [seg*64, seg*64+64)
    int c1 = 255, c2 = 255;                       // 255 == local INF (saturating)
    int ff1 = 255, ff2 = 255;
    int any = 0;
#pragma unroll 8
    for (int i = 0; i < 64; i++) {
        int mv = msk[(seg * 64 + i) * Ww];
        any |= mv;
        c1 = mv ? min(c1 + 1, 255) : 0;           // feature(fg pol) = ~mask
        c2 = mv ? 0 : min(c2 + 1, 255);           // feature(bg pol) =  mask
        if (!mv && ff1 == 255) ff1 = i;
        if (mv && ff2 == 255) ff2 = i;
        sfwd[seg * 64 + i][col] = (unsigned short)(c1 | (c2 << 8));
    }
    ssum[0][seg][col] = (unsigned short)(c1 | (c2 << 8));
    ssum[1][seg][col] = (unsigned short)(ff1 | (ff2 << 8));

    int anyb = __syncthreads_or(any);             // barrier + publishes smem
    if (tid == 0 && anyb) atomicOr(&g_hasfg[m], 1);

    // per-column feature flags + cross-segment carries
    int af1 = 0, af2 = 0;
#pragma unroll
    for (int s = 0; s < 4; s++) {
        unsigned int fp = ssum[1][s][col];
        af1 |= ((fp & 255u) != 255u);
        af2 |= (((fp >> 8) & 255u) != 255u);
    }
    // forward carry into this segment: cin(s) = min(sum(s-1), cin(s-1)+64)
    int cin1 = CFAKE, cin2 = CFAKE;
    for (int s = 0; s < seg; s++) {
        unsigned int sp = ssum[0][s][col];
        int s1 = sp & 255, s2 = (sp >> 8) & 255;
        cin1 = min((s1 == 255) ? CFAKE : s1, cin1 + 64);
        cin2 = min((s2 == 255) ? CFAKE : s2, cin2 + 64);
    }
    // backward carry: bin(s) = min(ff(s+1), bin(s+1)+64)
    int bin1 = CFAKE, bin2 = CFAKE;
    for (int s = 3; s > seg; s--) {
        unsigned int fp = ssum[1][s][col];
        int f1 = fp & 255, f2 = (fp >> 8) & 255;
        bin1 = min((f1 == 255) ? CFAKE : f1, bin1 + 64);
        bin2 = min((f2 == 255) ? CFAKE : f2, bin2 + 64);
    }

    // phase 2: backward local scan + combine + single write
    unsigned int* gout = g_g + (size_t)m * HW + w;
    int b1 = bin1, b2 = bin2;
#pragma unroll 8
    for (int i = 63; i >= 0; i--) {
        unsigned int fw = sfwd[seg * 64 + i][col];
        int f1 = fw & 255, f2 = (fw >> 8) & 255;
        b1 = (f1 == 0) ? 0 : b1 + 1;              // f==0 <=> feature here
        b2 = (f2 == 0) ? 0 : b2 + 1;
        int fa1 = min(f1, cin1 + i + 1);
        int fa2 = min(f2, cin2 + i + 1);
        int g1 = min(fa1, b1);
        int g2v = min(fa2, b2);
        unsigned int o1 = af1 ? (unsigned int)g1 : SENT16;
        unsigned int o2 = af2 ? (unsigned int)g2v : SENT16;
        gout[(seg * 64 + i) * Ww] = o1 | (o2 << 16);
    }
}

// ---------------- K3: exact windowed row pass -> field^2 ---------------------
__global__ void __launch_bounds__(256) k3_win() {
    __shared__ int sg2[8][768];                   // [warp][pad|data|pad]
    __shared__ unsigned char sub[8][256];
    __shared__ float sf2[4][256];

    int tid = threadIdx.x;
    int w = tid >> 5;
    int lane = tid & 31;
    int r = w >> 1;
    int pol = w & 1;
    int m = blockIdx.x;
    int row = blockIdx.y * 4 + r;

    if (!g_hasfg[m]) {                            // block-uniform
        float* o = g_f2 + (size_t)m * HW + (size_t)blockIdx.y * 4 * Ww;
        for (int i = tid; i < 4 * Ww; i += 256) o[i] = 0.0f;
        return;
    }

    const unsigned int* grow = g_g + (size_t)m * HW + (size_t)row * Ww;

#pragma unroll
    for (int i = lane; i < 768; i += 32) sg2[w][i] = BIGI;

    int base = lane * 8;
    const uint4* grow4 = (const uint4*)grow;
    uint4 q0 = grow4[lane * 2 + 0];
    uint4 q1 = grow4[lane * 2 + 1];
    unsigned int gp8[8] = {q0.x, q0.y, q0.z, q0.w, q1.x, q1.y, q1.z, q1.w};

    int x[8];
    int anyfin = 0;
#pragma unroll
    for (int i = 0; i < 8; i++) {
        unsigned int g = pol ? (gp8[i] >> 16) : (gp8[i] & 0xffffu);
        int fin = (g != SENT16);
        anyfin |= fin;
        sg2[w][256 + base + i] = fin ? (int)(g * g) : BIGI;
        x[i] = fin ? (int)g : 300;
    }

    float df[8];
    if (__ballot_sync(0xffffffffu, anyfin) == 0u) {
#pragma unroll
        for (int i = 0; i < 8; i++) df[i] = SENT_F;
    } else {
        // forward chamfer bound
        int f[8];
        int run = SCAN_INF;
#pragma unroll
        for (int i = 0; i < 8; i++) { run = min(x[i], run + 1); f[i] = run; }
        int v = run;
#pragma unroll
        for (int s = 1; s < 32; s <<= 1) {
            int o = __shfl_up_sync(0xffffffffu, v, s);
            if (lane >= s) v = min(v, o + 8 * s);
        }
        int e = __shfl_up_sync(0xffffffffu, v, 1);
        if (lane == 0) e = SCAN_INF;
#pragma unroll
        for (int i = 0; i < 8; i++) f[i] = min(f[i], e + 1 + i);

        // backward chamfer bound
        int bw[8];
        run = SCAN_INF;
#pragma unroll
        for (int i = 7; i >= 0; i--) { run = min(x[i], run + 1); bw[i] = run; }
        int vb = run;
#pragma unroll
        for (int s = 1; s < 32; s <<= 1) {
            int o = __shfl_down_sync(0xffffffffu, vb, s);
            if (lane + s < 32) vb = min(vb, o + 8 * s);
        }
        int eb = __shfl_down_sync(0xffffffffu, vb, 1);
        if (lane == 31) eb = SCAN_INF;
#pragma unroll
        for (int i = 0; i < 8; i++) {
            int ub = min(min(f[i], bw[i]), min(eb + 8 - i, 255));
            sub[w][base + i] = (unsigned char)ub;
        }
        __syncwarp();

        const int* gp = &sg2[w][256];
#pragma unroll
        for (int i = 0; i < 8; i++) {
            int j = i * 32 + lane;
            int R = (int)sub[w][j];
            R = __reduce_max_sync(0xffffffffu, R);
            int best = gp[j];
#pragma unroll 4
            for (int d = 1; d <= R; d++) {
                int cc1 = gp[j + d] + d * d;
                int cc2 = gp[j - d] + d * d;
                best = min(best, min(cc1, cc2));
            }
            df[i] = (best >= BIGI) ? SENT_F : (float)best;
        }
    }

    // combine polarities -> field^2 = a + b + 2*sqrt(a*b)
    if (pol) {
#pragma unroll
        for (int i = 0; i < 8; i++) sf2[r][i * 32 + lane] = df[i];
    }
    __syncthreads();
    if (!pol) {
        float* out = g_f2 + (size_t)m * HW + (size_t)row * Ww;
#pragma unroll
        for (int i = 0; i < 8; i++) {
            float a = df[i];
            float b = sf2[r][i * 32 + lane];
            out[i * 32 + lane] = a + b + 2.0f * __fsqrt_rn(a * b);
        }
    }
}

// ---------------- K4: loss reduction + last-block finalize -------------------
__global__ void k4_loss(const float* __restrict__ pred, const void* __restrict__ tgt,
                        float* __restrict__ outp) {
    int pix = blockIdx.x * 256 + threadIdx.x;
    int b = pix >> 16;
    int hw = pix & (HW - 1);
    const float* p = pred + (size_t)b * Cz * HW + hw;

    int t = load_target(tgt, pix);

    float v[Cz];
    float mx = -1e30f;
#pragma unroll
    for (int c = 0; c < Cz; c++) {
        v[c] = p[c * HW];
        mx = fmaxf(mx, v[c]);
    }
    float s = 0.0f;
#pragma unroll
    for (int c = 0; c < Cz; c++) {
        v[c] = expf(v[c] - mx);
        s += v[c];
    }
    float inv = 1.0f / s;

    double acc = 0.0;
#pragma unroll
    for (int c = 0; c < Cz; c++) {
        float fP2 = g_f2[(size_t)(b * Cz + c) * HW + hw];
        float fT2 = g_f2[(size_t)(HALFM + b * Cz + c) * HW + hw];
        float e = v[c] * inv - ((c == t) ? 1.0f : 0.0f);
        acc += (double)(e * e * (fP2 + fT2));
    }

    __shared__ double sred[256];
    sred[threadIdx.x] = acc;
    __syncthreads();
    for (int st = 128; st > 0; st >>= 1) {
        if (threadIdx.x < st) sred[threadIdx.x] += sred[threadIdx.x + st];
        __syncthreads();
    }
    if (threadIdx.x == 0) {
        atomicAdd(&g_acc[0], sred[0]);
        __threadfence();
        unsigned int prev = atomicAdd(&g_done, 1u);
        if (prev == (unsigned int)(gridDim.x - 1)) {
            __threadfence();
            volatile double* va = g_acc;
            double S = va[0];
            double CE = va[1];
            double N = (double)Bz * (double)HW;
            outp[0] = (float)(S / N / (double)Cz / (double)Bz / 3.0 - CE / N);
        }
    }
}

// ---------------- launch -----------------------------------------------------
extern "C" void kernel_launch(void* const* d_in, const int* in_sizes, int n_in,
                              void* d_out, int out_size) {
    const float* pred = (const float*)d_in[0];
    const void*  tgt  = d_in[1];
    float* out = (float*)d_out;

    k0_init<<<1, 128>>>((const unsigned int*)tgt);
    k1_masks<<<(Bz * HW) / 256, 256>>>(pred, tgt);
    k2_cols<<<dim3(NMASK, 4), 256>>>();
    k3_win<<<dim3(NMASK, Hh / 4), 256>>>();
    k4_loss<<<(Bz * HW) / 256, 256>>>(pred, tgt, out);
    (void)in_sizes; (void)n_in; (void)out_size;
}

// round 8
// speedup vs baseline: 6.9767x; 1.0363x over previous
#include <cuda_runtime.h>
#include <math.h>

#define Bz 4
#define Cz 12
#define Hh 256
#define Ww 256
#define HW 65536
#define NMASK 96
#define HALFM 48
#define SENT16 65535u
#define SENT_F 1e12f        // == fl32(1e6f*1e6f)
#define SCAN_INF (1 << 20)
#define CFAKE 10000
#define BIGU 0x0FFFFFFFu

// ---------------- scratch ----------------------------------------------------
__device__ unsigned char g_mask[NMASK * HW];
__device__ unsigned int  g_g[NMASK * HW];        // packed col dist (lo=fg, hi=bg)
__device__ float         g_f2[NMASK * HW];       // field^2 per mask
__device__ int           g_hasfg[NMASK];
__device__ int           g_anyfalse[NMASK];
__device__ double        g_acc[2];
__device__ int           g_is64;
__device__ unsigned int  g_done;

// ---------------- K0 ---------------------------------------------------------
__global__ void k0_init(const unsigned int* __restrict__ tgt_words) {
    int t = threadIdx.x;                          // 128 threads
    __shared__ int s_nz;
    if (t == 0) s_nz = 0;
    __syncthreads();
    if (tgt_words[2 * t + 1] != 0u) atomicOr(&s_nz, 1);
    if (t < NMASK) { g_hasfg[t] = 0; g_anyfalse[t] = 0; }
    __syncthreads();
    if (t == 0) {
        g_is64 = (s_nz == 0);
        g_acc[0] = 0.0;
        g_acc[1] = 0.0;
        g_done = 0u;
    }
}

__device__ __forceinline__ int load_target(const void* t, int idx) {
    if (g_is64) return (int)((const long long*)t)[idx];
    return ((const int*)t)[idx];
}

// ---------------- K1: softmax -> masks, CE partial ---------------------------
__global__ void k1_masks(const float* __restrict__ pred, const void* __restrict__ tgt) {
    int pix = blockIdx.x * 256 + threadIdx.x;
    int b = pix >> 16;
    int hw = pix & (HW - 1);
    const float* p = pred + (size_t)b * Cz * HW + hw;

    int t = load_target(tgt, pix);

    float v[Cz];
    float mx = -1e30f;
    float xt = 0.0f;
#pragma unroll
    for (int c = 0; c < Cz; c++) {
        v[c] = p[c * HW];
        mx = fmaxf(mx, v[c]);
        if (c == t) xt = v[c];
    }
    float s = 0.0f;
#pragma unroll
    for (int c = 0; c < Cz; c++) {
        v[c] = expf(v[c] - mx);
        s += v[c];
    }
    float inv = 1.0f / s;
#pragma unroll
    for (int c = 0; c < Cz; c++) {
        g_mask[(size_t)(b * Cz + c) * HW + hw] = (unsigned char)(v[c] * inv > 0.5f);
        g_mask[(size_t)(HALFM + b * Cz + c) * HW + hw] = (unsigned char)(c == t);
    }

    float logp = xt - mx - logf(s);

    __shared__ float sred[256];
    sred[threadIdx.x] = logp;
    __syncthreads();
    for (int st = 128; st > 0; st >>= 1) {
        if (threadIdx.x < st) sred[threadIdx.x] += sred[threadIdx.x + st];
        __syncthreads();
    }
    if (threadIdx.x == 0) atomicAdd(&g_acc[1], (double)sred[0]);
}

// ---------------- K2: segmented column EDT (exact) ---------------------------
__global__ void __launch_bounds__(256) k2_cols() {
    __shared__ unsigned short sfwd[Hh][64];
    __shared__ unsigned short ssum[2][4][64];

    int tid = threadIdx.x;
    int col = tid & 63;
    int seg = tid >> 6;
    int m = blockIdx.x;
    int w = blockIdx.y * 64 + col;
    const unsigned char* msk = g_mask + (size_t)m * HW + w;

    int c1 = 255, c2 = 255;
    int ff1 = 255, ff2 = 255;
    int any = 0, anyf = 0;
#pragma unroll 8
    for (int i = 0; i < 64; i++) {
        int mv = msk[(seg * 64 + i) * Ww];
        any |= mv;
        anyf |= (mv ^ 1);
        c1 = mv ? min(c1 + 1, 255) : 0;
        c2 = mv ? 0 : min(c2 + 1, 255);
        if (!mv && ff1 == 255) ff1 = i;
        if (mv && ff2 == 255) ff2 = i;
        sfwd[seg * 64 + i][col] = (unsigned short)(c1 | (c2 << 8));
    }
    ssum[0][seg][col] = (unsigned short)(c1 | (c2 << 8));
    ssum[1][seg][col] = (unsigned short)(ff1 | (ff2 << 8));

    int anyb = __syncthreads_or(any);
    if (tid == 0 && anyb) atomicOr(&g_hasfg[m], 1);
    int anyfb = __syncthreads_or(anyf);
    if (tid == 0 && anyfb) atomicOr(&g_anyfalse[m], 1);

    int af1 = 0, af2 = 0;
#pragma unroll
    for (int s = 0; s < 4; s++) {
        unsigned int fp = ssum[1][s][col];
        af1 |= ((fp & 255u) != 255u);
        af2 |= (((fp >> 8) & 255u) != 255u);
    }
    int cin1 = CFAKE, cin2 = CFAKE;
    for (int s = 0; s < seg; s++) {
        unsigned int sp = ssum[0][s][col];
        int s1 = sp & 255, s2 = (sp >> 8) & 255;
        cin1 = min((s1 == 255) ? CFAKE : s1, cin1 + 64);
        cin2 = min((s2 == 255) ? CFAKE : s2, cin2 + 64);
    }
    int bin1 = CFAKE, bin2 = CFAKE;
    for (int s = 3; s > seg; s--) {
        unsigned int fp = ssum[1][s][col];
        int f1 = fp & 255, f2 = (fp >> 8) & 255;
        bin1 = min((f1 == 255) ? CFAKE : f1, bin1 + 64);
        bin2 = min((f2 == 255) ? CFAKE : f2, bin2 + 64);
    }

    unsigned int* gout = g_g + (size_t)m * HW + w;
    int b1 = bin1, b2 = bin2;
#pragma unroll 8
    for (int i = 63; i >= 0; i--) {
        unsigned int fw = sfwd[seg * 64 + i][col];
        int f1 = fw & 255, f2 = (fw >> 8) & 255;
        b1 = (f1 == 0) ? 0 : b1 + 1;
        b2 = (f2 == 0) ? 0 : b2 + 1;
        int fa1 = min(f1, cin1 + i + 1);
        int fa2 = min(f2, cin2 + i + 1);
        int g1 = min(fa1, b1);
        int g2v = min(fa2, b2);
        unsigned int o1 = af1 ? (unsigned int)g1 : SENT16;
        unsigned int o2 = af2 ? (unsigned int)g2v : SENT16;
        gout[(seg * 64 + i) * Ww] = o1 | (o2 << 16);
    }
}

// ---------------- K3: u16-packed 2-row exact window scan -> field^2 ----------
// Block: 8 warps = 4 row-pairs x 2 polarities; block covers 8 rows.
// Each warp: 2 adjacent rows, one polarity, g^2 packed as u16 pairs in smem.
__global__ void __launch_bounds__(256) k3_win() {
    __shared__ unsigned int sg[8][768];           // [warp][256 pad | 256 data | 256 pad]
    __shared__ unsigned char sub[8][256];
    __shared__ float sf2[8][256];

    int tid = threadIdx.x;
    int w = tid >> 5;
    int lane = tid & 31;
    int pair = w >> 1;
    int pol = w & 1;
    int m = blockIdx.x;

    int hfg = g_hasfg[m];
    int afl = g_anyfalse[m];
    if (!hfg || !afl) {                           // empty mask -> 0; all-true -> SENT_F
        float val = hfg ? SENT_F : 0.0f;
        float* o = g_f2 + (size_t)m * HW + (size_t)blockIdx.y * 8 * Ww;
        for (int i = tid; i < 8 * Ww; i += 256) o[i] = val;
        return;
    }

    int r0g = blockIdx.y * 8 + pair * 2;
    const unsigned int* g0 = g_g + (size_t)m * HW + (size_t)r0g * Ww;

    // pads = saturated-inf
    for (int i = lane; i < 256; i += 32) {
        sg[w][i] = 0xFFFFFFFFu;
        sg[w][512 + i] = 0xFFFFFFFFu;
    }

    const uint4* a0 = (const uint4*)g0;
    const uint4* a1 = (const uint4*)(g0 + Ww);
    uint4 w00 = a0[lane * 2], w01 = a0[lane * 2 + 1];
    uint4 w10 = a1[lane * 2], w11 = a1[lane * 2 + 1];
    unsigned int r0w[8] = {w00.x, w00.y, w00.z, w00.w, w01.x, w01.y, w01.z, w01.w};
    unsigned int r1w[8] = {w10.x, w10.y, w10.z, w10.w, w11.x, w11.y, w11.z, w11.w};

    int x[8];
    int base = lane * 8;
#pragma unroll
    for (int i = 0; i < 8; i++) {
        unsigned int ga = pol ? (r0w[i] >> 16) : (r0w[i] & 0xffffu);
        unsigned int gb = pol ? (r1w[i] >> 16) : (r1w[i] & 0xffffu);
        unsigned int q0 = (ga == 0xffffu) ? 0xffffu : ga * ga;   // u16 exact (<=65025)
        unsigned int q1 = (gb == 0xffffu) ? 0xffffu : gb * gb;
        sg[w][256 + base + i] = q0 | (q1 << 16);
        x[i] = (int)min(ga, 300u);                // >=256 cap is exact (R clamps at 255)
    }

    // chamfer bound on row0 (scalar); row1 covered by ub+1 (metric inequality)
    int f[8];
    int run = SCAN_INF;
#pragma unroll
    for (int i = 0; i < 8; i++) { run = min(x[i], run + 1); f[i] = run; }
    int v = run;
#pragma unroll
    for (int s = 1; s < 32; s <<= 1) {
        int o = __shfl_up_sync(0xffffffffu, v, s);
        if (lane >= s) v = min(v, o + 8 * s);
    }
    int e = __shfl_up_sync(0xffffffffu, v, 1);
    if (lane == 0) e = SCAN_INF;
#pragma unroll
    for (int i = 0; i < 8; i++) f[i] = min(f[i], e + 1 + i);

    int bw[8];
    run = SCAN_INF;
#pragma unroll
    for (int i = 7; i >= 0; i--) { run = min(x[i], run + 1); bw[i] = run; }
    int vb = run;
#pragma unroll
    for (int s = 1; s < 32; s <<= 1) {
        int o = __shfl_down_sync(0xffffffffu, vb, s);
        if (lane + s < 32) vb = min(vb, o + 8 * s);
    }
    int eb = __shfl_down_sync(0xffffffffu, vb, 1);
    if (lane == 31) eb = SCAN_INF;
#pragma unroll
    for (int i = 0; i < 8; i++) {
        int ub = min(min(f[i], bw[i]), min(eb + 8 - i, 255));
        sub[w][base + i] = (unsigned char)min(ub + 1, 255);
    }
    __syncwarp();

    // main packed loop
    const unsigned int* gp = &sg[w][256];
    float dfa[8], dfb[8];
#pragma unroll
    for (int i = 0; i < 8; i++) {
        int j = i * 32 + lane;
        unsigned int R = sub[w][j];
        R = __reduce_max_sync(0xffffffffu, R);
        unsigned int best = gp[j];
        unsigned int dd2 = 0u, inc2 = 0x00010001u;
        int nb = ((int)R + 7) >> 3;
        int dbase = 0;
        for (int bl = 0; bl < nb; bl++) {
#pragma unroll
            for (int u = 1; u <= 8; u++) {
                int d = dbase + u;                // d <= 256; index in [0,767] safe
                dd2 += inc2; inc2 += 0x00020002u; // dd2 = d^2 per half
                unsigned int ca = gp[j + d];
                unsigned int cb = gp[j - d];
                unsigned int c = __vminu2(ca, cb);
                best = __vminu2(best, __vaddus2(c, dd2));
            }
            dbase += 8;
            // exact early exit: remaining candidates >= (dbase+1)^2
            unsigned int hm = max(best & 0xffffu, best >> 16);
            hm = __reduce_max_sync(0xffffffffu, hm);
            if ((unsigned int)((dbase + 1) * (dbase + 1)) >= hm) break;
        }
        unsigned int h0 = best & 0xffffu, h1 = best >> 16;
        int ov = (h0 == 0xffffu) | (h1 == 0xffffu);
        if (__ballot_sync(0xffffffffu, ov)) {
            // exact u32 fallback (rare: true EDT^2 > 65535 -> R was 255)
            unsigned int b0 = BIGU, b1 = BIGU;
            for (int d = 0; d <= 255; d++) {
                unsigned int ds = (unsigned int)(d * d);
                unsigned int pa = gp[j + d], pb = gp[j - d];
                unsigned int v0 = pa & 0xffffu; v0 = (v0 == 0xffffu) ? BIGU : v0 + ds;
                unsigned int v1 = pa >> 16;     v1 = (v1 == 0xffffu) ? BIGU : v1 + ds;
                unsigned int u0 = pb & 0xffffu; u0 = (u0 == 0xffffu) ? BIGU : u0 + ds;
                unsigned int u1 = pb >> 16;     u1 = (u1 == 0xffffu) ? BIGU : u1 + ds;
                b0 = min(b0, min(v0, u0));
                b1 = min(b1, min(v1, u1));
            }
            dfa[i] = (float)((h0 == 0xffffu) ? b0 : h0);
            dfb[i] = (float)((h1 == 0xffffu) ? b1 : h1);
        } else {
            dfa[i] = (float)h0;
            dfb[i] = (float)h1;
        }
    }

    // polarity exchange + combine: field^2 = a + b + 2*sqrt(a*b)
    int lr = pair * 2;
    if (pol) {
#pragma unroll
        for (int i = 0; i < 8; i++) {
            sf2[lr][i * 32 + lane] = dfa[i];
            sf2[lr + 1][i * 32 + lane] = dfb[i];
        }
    }
    __syncthreads();
    if (!pol) {
        float* o0 = g_f2 + (size_t)m * HW + (size_t)r0g * Ww;
        float* o1 = o0 + Ww;
#pragma unroll
        for (int i = 0; i < 8; i++) {
            int j = i * 32 + lane;
            float a = dfa[i], b = sf2[lr][j];
            o0[j] = a + b + 2.0f * __fsqrt_rn(a * b);
            float a2 = dfb[i], b2v = sf2[lr + 1][j];
            o1[j] = a2 + b2v + 2.0f * __fsqrt_rn(a2 * b2v);
        }
    }
}

// ---------------- K4: loss reduction + last-block finalize -------------------
__global__ void k4_loss(const float* __restrict__ pred, const void* __restrict__ tgt,
                        float* __restrict__ outp) {
    int pix = blockIdx.x * 256 + threadIdx.x;
    int b = pix >> 16;
    int hw = pix & (HW - 1);
    const float* p = pred + (size_t)b * Cz * HW + hw;

    int t = load_target(tgt, pix);

    float v[Cz];
    float mx = -1e30f;
#pragma unroll
    for (int c = 0; c < Cz; c++) {
        v[c] = p[c * HW];
        mx = fmaxf(mx, v[c]);
    }
    float s = 0.0f;
#pragma unroll
    for (int c = 0; c < Cz; c++) {
        v[c] = expf(v[c] - mx);
        s += v[c];
    }
    float inv = 1.0f / s;

    double acc = 0.0;
#pragma unroll
    for (int c = 0; c < Cz; c++) {
        float fP2 = g_f2[(size_t)(b * Cz + c) * HW + hw];
        float fT2 = g_f2[(size_t)(HALFM + b * Cz + c) * HW + hw];
        float e = v[c] * inv - ((c == t) ? 1.0f : 0.0f);
        acc += (double)(e * e * (fP2 + fT2));
    }

    __shared__ double sred[256];
    sred[threadIdx.x] = acc;
    __syncthreads();
    for (int st = 128; st > 0; st >>= 1) {
        if (threadIdx.x < st) sred[threadIdx.x] += sred[threadIdx.x + st];
        __syncthreads();
    }
    if (threadIdx.x == 0) {
        atomicAdd(&g_acc[0], sred[0]);
        __threadfence();
        unsigned int prev = atomicAdd(&g_done, 1u);
        if (prev == (unsigned int)(gridDim.x - 1)) {
            __threadfence();
            volatile double* va = g_acc;
            double S = va[0];
            double CE = va[1];
            double N = (double)Bz * (double)HW;
            outp[0] = (float)(S / N / (double)Cz / (double)Bz / 3.0 - CE / N);
        }
    }
}

// ---------------- launch -----------------------------------------------------
extern "C" void kernel_launch(void* const* d_in, const int* in_sizes, int n_in,
                              void* d_out, int out_size) {
    const float* pred = (const float*)d_in[0];
    const void*  tgt  = d_in[1];
    float* out = (float*)d_out;

    k0_init<<<1, 128>>>((const unsigned int*)tgt);
    k1_masks<<<(Bz * HW) / 256, 256>>>(pred, tgt);
    k2_cols<<<dim3(NMASK, 4), 256>>>();
    k3_win<<<dim3(NMASK, Hh / 8), 256>>>();
    k4_loss<<<(Bz * HW) / 256, 256>>>(pred, tgt, out);
    (void)in_sizes; (void)n_in; (void)out_size;
}